// round 16
// baseline (speedup 1.0000x reference)
#include <cuda_runtime.h>
#include <cuda_bf16.h>

// FocalLoss, PPT=2 persistent grid (R12 winner) + MUFU-halving:
//   sp = log1p(exp(-|x|)) computed as  u = __expf(-|x|); sp = P6(u)
//   where P6 is a degree-6 Chebyshev-derived minimax poly for log1p on [0,1]
//   (abs err ~1.5e-6). Removes the LG2 MUFU op (XU pipe was ~66% busy).
//   t=0 term: f0(x) = x^2 * (relu(x) + sp);  label-channel corr: f1 - f0,
//   f1(x) = (1-x)^2 * (relu(-x) + sp).  loss = ALPHA * mean(V * (sum f0 + corr))
// N=4, C=19, H=W=512. Labels int32 (JAX x32 default).

#define NCLS 19
#define HW_SZ (512 * 512)          // 2^18
#define PIX_TOTAL (4 * 512 * 512)  // 2^20 pixels
#define PPT 2
#define NGROUPS (PIX_TOTAL / PPT)  // 524288
#define ALPHA_F 0.25f
#define TOTAL_ELEMS ((long long)4 * NCLS * 512 * 512)
#define NUM_SMS 148
#define CTAS_PER_SM 8
#define NBLOCKS (NUM_SMS * CTAS_PER_SM)  // 1184

__global__ void zero_out_kernel(float* out) {
    if (threadIdx.x == 0) out[0] = 0.0f;
}

// log1p(u) on [0,1], degree-6, abs err ~1.5e-6 (from Chebyshev series of
// log(3+x), r = 3-2sqrt(2); endpoint checks: P(0)=+1.5e-6, P(1)=ln2-1.1e-6).
__device__ __forceinline__ float log1p_poly(float u) {
    float p = fmaf(-0.01740800f, u, 0.08267264f);
    p = fmaf(p, u, -0.19033344f);
    p = fmaf(p, u,  0.31573696f);
    p = fmaf(p, u, -0.49737112f);
    p = fmaf(p, u,  0.99984760f);
    p = fmaf(p, u,  0.00000146f);
    return p;
}

__device__ __forceinline__ float softplus_neg_abs(float x) {
    // log1p(exp(-|x|)) with a single MUFU (EX2); LG2 replaced by polynomial.
    return log1p_poly(__expf(-fabsf(x)));
}

__global__ __launch_bounds__(256) void focal_loss_kernel(
    const float* __restrict__ x,     // [N,C,H,W]
    const int*   __restrict__ label, // [N,H,W] int32
    float* __restrict__ out)
{
    const int tid0    = blockIdx.x * blockDim.x + threadIdx.x;
    const int nthread = gridDim.x * blockDim.x;   // 303104
    float acc = 0.0f;

    for (int g = tid0; g < NGROUPS; g += nthread) {
        const int p2 = g * PPT;
        const int n  = p2 >> 18;
        const int hw = p2 & (HW_SZ - 1);

        const int2 lv = *reinterpret_cast<const int2*>(label + p2);
        const int L[PPT] = { lv.x, lv.y };

        const size_t base = (size_t)n * (NCLS * HW_SZ) + hw;

        // ---- uniform t=0 sum over 19 channels, one float2 per channel ----
        float S0[PPT] = {0.f, 0.f};
        #pragma unroll
        for (int c = 0; c < NCLS; c++) {
            const float2 xv = *reinterpret_cast<const float2*>(x + base + (size_t)c * HW_SZ);
            const float xs[PPT] = { xv.x, xv.y };
            #pragma unroll
            for (int i = 0; i < PPT; i++) {
                const float xi = xs[i];
                const float p  = fmaxf(xi, 0.0f) + softplus_neg_abs(xi);
                S0[i] = fmaf(xi * xi, p, S0[i]);
            }
        }

        // ---- per-pixel correction at the label channel (L1/L2 hits) ----
        #pragma unroll
        for (int i = 0; i < PPT; i++) {
            const bool valid = (L[i] >= 0 && L[i] != 255);
            const int  Ls    = valid ? L[i] : 0;
            const float xl   = x[base + ((size_t)Ls << 18) + i];
            const float sp   = softplus_neg_abs(xl);
            const float omx  = 1.0f - xl;
            const float f1   = omx * omx * (fmaxf(-xl, 0.0f) + sp);
            const float f0   = xl * xl * (fmaxf(xl, 0.0f) + sp);
            const float V    = valid ? 1.0f : 0.0f;
            acc = fmaf(V, S0[i] + (f1 - f0), acc);
        }
    }

    // Warp reduction
    #pragma unroll
    for (int o = 16; o > 0; o >>= 1)
        acc += __shfl_xor_sync(0xffffffffu, acc, o);

    __shared__ float warp_sums[8];
    const int lane = threadIdx.x & 31;
    const int wid  = threadIdx.x >> 5;
    if (lane == 0) warp_sums[wid] = acc;
    __syncthreads();

    if (wid == 0) {
        float v = (lane < 8) ? warp_sums[lane] : 0.0f;
        #pragma unroll
        for (int o = 4; o > 0; o >>= 1)
            v += __shfl_xor_sync(0xffffffffu, v, o);
        if (lane == 0) {
            const float scale = ALPHA_F / (float)TOTAL_ELEMS;  // LOSS_WEIGHT=1
            atomicAdd(out, v * scale);
        }
    }
}

extern "C" void kernel_launch(void* const* d_in, const int* in_sizes, int n_in,
                              void* d_out, int out_size) {
    const float* cls_score = (const float*)d_in[0];
    const int*   label     = (const int*)d_in[1];
    float* out = (float*)d_out;

    zero_out_kernel<<<1, 32>>>(out);
    focal_loss_kernel<<<NBLOCKS, 256>>>(cls_score, label, out);
}